// round 4
// baseline (speedup 1.0000x reference)
#include <cuda_runtime.h>
#include <stdint.h>

// BNB 8-bit embedding dequant gather:
//   out[token,:] = (float)q_weight[x[token],:] * (absmax[x[token]] / 127)
//
// NOTE: the harness materializes int8 q_weight as INT32 on device (supported
// dtypes are f32/i32/bf16). So q_weight is [50257,1024] int32, one quantized
// value per element. x[32768] i32, absmax[50257] f32, out[32768,1024] f32.
//
// Inputs bound by element count (mutually distinct): qw=51463168 (largest),
// x=32768 (smallest), absmax=50257.

static constexpr int DIM = 1024;
static constexpr int THREADS = 256;  // DIM/4 int4 lanes

__global__ __launch_bounds__(THREADS, 8)
void bnb8_embed_kernel(const int* __restrict__ x,
                       const int* __restrict__ qw,
                       const float* __restrict__ absmax,
                       float* __restrict__ out,
                       int n_tokens)
{
    const int token = blockIdx.x;
    if (token >= n_tokens) return;

    __shared__ float s_scale;
    __shared__ int s_row;
    if (threadIdx.x == 0) {
        int row = __ldg(x + token);
        s_row = row;
        s_scale = __ldg(absmax + row) * (1.0f / 127.0f);
    }
    __syncthreads();

    const int row = s_row;
    const float scale = s_scale;

    // Each thread: 4 int32 quant values in (16B), 4 f32 out (16B). Coalesced.
    const int4* rp = reinterpret_cast<const int4*>(qw + (long long)row * DIM);
    int4 v = __ldg(rp + threadIdx.x);

    float4 o;
    o.x = (float)v.x * scale;
    o.y = (float)v.y * scale;
    o.z = (float)v.z * scale;
    o.w = (float)v.w * scale;

    float4* op = reinterpret_cast<float4*>(out + (long long)token * DIM);
    op[threadIdx.x] = o;
}

extern "C" void kernel_launch(void* const* d_in, const int* in_sizes, int n_in,
                              void* d_out, int out_size)
{
    // Bind by element count: qw largest, x smallest, absmax the remaining one.
    long long max_sz = -1;
    int qw_idx = -1;
    for (int i = 0; i < n_in; i++)
        if ((long long)in_sizes[i] > max_sz) { max_sz = in_sizes[i]; qw_idx = i; }

    long long min_sz = 0x7fffffffffffLL;
    int x_idx = -1;
    for (int i = 0; i < n_in; i++) {
        if (i == qw_idx) continue;
        if ((long long)in_sizes[i] < min_sz) { min_sz = in_sizes[i]; x_idx = i; }
    }
    int am_idx = -1;
    for (int i = 0; i < n_in; i++)
        if (i != qw_idx && i != x_idx) am_idx = i;

    const int*   x      = (const int*)d_in[x_idx];
    const int*   qw     = (const int*)d_in[qw_idx];
    const float* absmax = (const float*)d_in[am_idx];
    float*       out    = (float*)d_out;
    const int n_tokens  = in_sizes[x_idx];  // 32768

    bnb8_embed_kernel<<<n_tokens, THREADS>>>(x, qw, absmax, out, n_tokens);
}

// round 5
// speedup vs baseline: 1.3351x; 1.3351x over previous
#include <cuda_runtime.h>
#include <stdint.h>

// BNB 8-bit embedding dequant gather (harness materializes int8 q_weight as int32):
//   out[token,:] = (float)q_weight[x[token],:] * (absmax[x[token]] / 127)
// x[32768] i32, q_weight[50257,1024] i32, absmax[50257] f32, out[32768,1024] f32.
//
// Latency-optimized: 4 tokens per CTA, each thread issues 4 independent int4
// gathers front-to-back (MLP=4), no barrier, streaming stores (__stcs) to keep
// L2 for the gather table.

static constexpr int DIM = 1024;
static constexpr int THREADS = 256;        // DIM/4 int4 lanes
static constexpr int TOKENS_PER_CTA = 4;

__global__ __launch_bounds__(THREADS)
void bnb8_embed_kernel(const int* __restrict__ x,
                       const int* __restrict__ qw,
                       const float* __restrict__ absmax,
                       float* __restrict__ out,
                       int n_tokens)
{
    const int base = blockIdx.x * TOKENS_PER_CTA;

    // Broadcast index loads (same addr across CTA -> 1 request + broadcast).
    int rows[TOKENS_PER_CTA];
#pragma unroll
    for (int i = 0; i < TOKENS_PER_CTA; i++)
        rows[i] = __ldg(x + base + i);

    float scales[TOKENS_PER_CTA];
#pragma unroll
    for (int i = 0; i < TOKENS_PER_CTA; i++)
        scales[i] = __ldg(absmax + rows[i]) * (1.0f / 127.0f);

    // 4 independent 16B gathers in flight before any consumption.
    int4 v[TOKENS_PER_CTA];
#pragma unroll
    for (int i = 0; i < TOKENS_PER_CTA; i++) {
        const int4* rp = reinterpret_cast<const int4*>(qw + (long long)rows[i] * DIM);
        v[i] = __ldg(rp + threadIdx.x);
    }

#pragma unroll
    for (int i = 0; i < TOKENS_PER_CTA; i++) {
        float4 o;
        o.x = (float)v[i].x * scales[i];
        o.y = (float)v[i].y * scales[i];
        o.z = (float)v[i].z * scales[i];
        o.w = (float)v[i].w * scales[i];
        float4* op = reinterpret_cast<float4*>(out + (long long)(base + i) * DIM);
        __stcs(op + threadIdx.x, o);   // evict-first: output never re-read
    }
}

extern "C" void kernel_launch(void* const* d_in, const int* in_sizes, int n_in,
                              void* d_out, int out_size)
{
    // Bind by element count: qw largest, x smallest, absmax the remaining one.
    long long max_sz = -1;
    int qw_idx = -1;
    for (int i = 0; i < n_in; i++)
        if ((long long)in_sizes[i] > max_sz) { max_sz = in_sizes[i]; qw_idx = i; }

    long long min_sz = 0x7fffffffffffLL;
    int x_idx = -1;
    for (int i = 0; i < n_in; i++) {
        if (i == qw_idx) continue;
        if ((long long)in_sizes[i] < min_sz) { min_sz = in_sizes[i]; x_idx = i; }
    }
    int am_idx = -1;
    for (int i = 0; i < n_in; i++)
        if (i != qw_idx && i != x_idx) am_idx = i;

    const int*   x      = (const int*)d_in[x_idx];
    const int*   qw     = (const int*)d_in[qw_idx];
    const float* absmax = (const float*)d_in[am_idx];
    float*       out    = (float*)d_out;
    const int n_tokens  = in_sizes[x_idx];  // 32768

    const int grid = (n_tokens + TOKENS_PER_CTA - 1) / TOKENS_PER_CTA;
    bnb8_embed_kernel<<<grid, THREADS>>>(x, qw, absmax, out, n_tokens);
}